// round 1
// baseline (speedup 1.0000x reference)
#include <cuda_runtime.h>
#include <math.h>

#define FULL 0xFFFFFFFFu

// One warp per 64x64 SPD matrix. Lane k holds two full columns of W (init W=P)
// in registers: u = column at ring position k, v = column at position 63-k.
// One-sided Jacobi: rotate column pairs to orthogonality; converged columns are
// lambda_p * u_p. Output X = sum_p (0.5*log(d_p)/d_p) w_p w_p^T, d_p = ||w_p||^2.
__global__ __launch_bounds__(32) void logeig_jacobi(const float* __restrict__ P,
                                                    float* __restrict__ X,
                                                    int nmat) {
    const int m = blockIdx.x;
    if (m >= nmat) return;
    const int k = threadIdx.x;            // lane 0..31
    const float* __restrict__ Pm = P + (size_t)m * 4096;
    float* __restrict__ Xm = X + (size_t)m * 4096;

    float u[64], v[64];
#pragma unroll
    for (int i = 0; i < 64; ++i) {
        // column c of P: elements P[i*64 + c]; coalesced across lanes
        u[i] = Pm[i * 64 + k];
        v[i] = Pm[i * 64 + (63 - k)];
    }

    // column norms^2, carried incrementally through rotations/exchanges
    float du = 0.f, dv = 0.f;
#pragma unroll
    for (int i = 0; i < 64; ++i) {
        du = fmaf(u[i], u[i], du);
        dv = fmaf(v[i], v[i], dv);
    }

    for (int sweep = 0; sweep < 16; ++sweep) {
        unsigned any = 0u;
        for (int r = 0; r < 63; ++r) {
            // cross dot product x = <u, v>
            float x = 0.f;
#pragma unroll
            for (int i = 0; i < 64; ++i) x = fmaf(u[i], v[i], x);

            // relative convergence threshold (one-sided Jacobi, high rel. accuracy)
            bool rot = (x * x > 1e-12f * du * dv);
            any |= __ballot_sync(FULL, rot);

            float xd  = rot ? x : 1.0f;                    // avoid div-by-zero
            float tau = (dv - du) / (2.0f * xd);
            float t   = copysignf(1.0f, tau) /
                        (fabsf(tau) + sqrtf(fmaf(tau, tau, 1.0f)));
            float c   = rsqrtf(fmaf(t, t, 1.0f));
            float s   = t * c;
            if (!rot) { c = 1.0f; s = 0.0f; t = 0.0f; }

            float ndu = fmaf(-t, x, du);                   // exact update when
            float ndv = fmaf( t, x, dv);                   // off-diag is zeroed

            // rotate columns + Brent-Luk ring exchange (tournament rotation:
            // position 0 fixed; positions 1..63 cycle i->i+1).
            //   new_top[0]    = top[0]
            //   new_top[1]    = bottom[0]
            //   new_top[k>=2] = top[k-1]
            //   new_bot[k<31] = bottom[k+1]
            //   new_bot[31]   = top[31]
#pragma unroll
            for (int i = 0; i < 64; ++i) {
                float un = fmaf(c, u[i], -(s * v[i]));
                float vn = fmaf(s, u[i],   c * v[i]);
                float su = (k == 0) ? vn : un;             // lane0 forwards bottom
                float tu = __shfl_up_sync(FULL, su, 1);
                float tv = __shfl_down_sync(FULL, vn, 1);
                u[i] = (k == 0)  ? un : tu;
                v[i] = (k == 31) ? un : tv;
            }
            // carry the norms with their columns
            {
                float sdu = (k == 0) ? ndv : ndu;
                float tdu = __shfl_up_sync(FULL, sdu, 1);
                float tdv = __shfl_down_sync(FULL, ndv, 1);
                du = (k == 0)  ? ndu : tdu;
                dv = (k == 31) ? ndu : tdv;
            }
        }
        if (any == 0u) break;                              // full sweep, no rotations
    }

    // exact final norms for the log weights
    float fdu = 0.f, fdv = 0.f;
#pragma unroll
    for (int i = 0; i < 64; ++i) {
        fdu = fmaf(u[i], u[i], fdu);
        fdv = fmaf(v[i], v[i], fdv);
    }

    // Stage converged columns into shared (as rows, padded: conflict-free) and
    // assemble X = W diag(g) W^T, g_p = 0.5*log(d_p)/d_p  (sigma_p^2 = d_p,
    // lambda_p = sigma_p, u_p = w_p/sigma_p).
    __shared__ float W[64][65];
    __shared__ float g[64];
#pragma unroll
    for (int i = 0; i < 64; ++i) {
        W[k][i]      = u[i];
        W[k + 32][i] = v[i];
    }
    g[k]      = 0.5f * logf(fdu) / fdu;
    g[k + 32] = 0.5f * logf(fdv) / fdv;
    __syncwarp();

    // lane k computes output columns k and k+32 (coalesced stores)
    float acc[64];
#pragma unroll
    for (int i = 0; i < 64; ++i) acc[i] = 0.f;
    for (int p = 0; p < 64; ++p) {
        float sp = g[p] * W[p][k];          // conflict-free (consecutive lanes)
#pragma unroll
        for (int i = 0; i < 64; ++i)
            acc[i] = fmaf(sp, W[p][i], acc[i]);  // broadcast loads
    }
#pragma unroll
    for (int i = 0; i < 64; ++i) Xm[i * 64 + k] = acc[i];

#pragma unroll
    for (int i = 0; i < 64; ++i) acc[i] = 0.f;
    for (int p = 0; p < 64; ++p) {
        float sp = g[p] * W[p][k + 32];
#pragma unroll
        for (int i = 0; i < 64; ++i)
            acc[i] = fmaf(sp, W[p][i], acc[i]);
    }
#pragma unroll
    for (int i = 0; i < 64; ++i) Xm[i * 64 + (k + 32)] = acc[i];
}

extern "C" void kernel_launch(void* const* d_in, const int* in_sizes, int n_in,
                              void* d_out, int out_size) {
    const float* P = (const float*)d_in[0];
    float* X = (float*)d_out;
    int nmat = in_sizes[0] / 4096;          // 64*64 per matrix (B*H = 8192)
    logeig_jacobi<<<nmat, 32>>>(P, X, nmat);
}

// round 2
// speedup vs baseline: 1.3439x; 1.3439x over previous
#include <cuda_runtime.h>
#include <math.h>

#define FULL 0xFFFFFFFFu
typedef unsigned long long u64;

// ---- packed f32x2 helpers (sm_103a) ------------------------------------
__device__ __forceinline__ u64 pk2(float lo, float hi) {
    u64 r; asm("mov.b64 %0, {%1, %2};" : "=l"(r) : "f"(lo), "f"(hi)); return r;
}
__device__ __forceinline__ float lo2(u64 x) { return __uint_as_float((unsigned)x); }
__device__ __forceinline__ float hi2(u64 x) { return __uint_as_float((unsigned)(x >> 32)); }
__device__ __forceinline__ u64 fma2(u64 a, u64 b, u64 c) {
    u64 d; asm("fma.rn.f32x2 %0, %1, %2, %3;" : "=l"(d) : "l"(a), "l"(b), "l"(c)); return d;
}
__device__ __forceinline__ u64 mul2(u64 a, u64 b) {
    u64 d; asm("mul.rn.f32x2 %0, %1, %2;" : "=l"(d) : "l"(a), "l"(b)); return d;
}
__device__ __forceinline__ u64 shfl64(u64 x, int src) {
    unsigned lo = (unsigned)x, hi = (unsigned)(x >> 32);
    lo = __shfl_sync(FULL, lo, src);
    hi = __shfl_sync(FULL, hi, src);
    return ((u64)hi << 32) | (u64)lo;
}
__device__ __forceinline__ u64 shfl64x(u64 x, int mask) {
    unsigned lo = (unsigned)x, hi = (unsigned)(x >> 32);
    lo = __shfl_xor_sync(FULL, lo, mask);
    hi = __shfl_xor_sync(FULL, hi, mask);
    return ((u64)hi << 32) | (u64)lo;
}

// One warp per 64x64 SPD matrix. Lane k holds two columns (u, v) packed as
// 32 x f32x2 each. One-sided Jacobi with a recursive-halving tournament:
// at level g (group of g lanes, 2g columns), u stays fixed and v cycles
// within the group -> 64+1 shuffles/round, no boundary selects.
__global__ __launch_bounds__(32) void logeig_jacobi(const float* __restrict__ P,
                                                    float* __restrict__ X,
                                                    int nmat) {
    const int m = blockIdx.x;
    if (m >= nmat) return;
    const int k = threadIdx.x;
    const float* __restrict__ Pm = P + (size_t)m * 4096;
    float* __restrict__ Xm = X + (size_t)m * 4096;

    u64 U[32], V[32];
#pragma unroll
    for (int j = 0; j < 32; ++j) {
        // column c elements i: Pm[i*64 + c]; pack element pair (2j, 2j+1)
        U[j] = pk2(Pm[(2 * j) * 64 + k],        Pm[(2 * j + 1) * 64 + k]);
        V[j] = pk2(Pm[(2 * j) * 64 + (k + 32)], Pm[(2 * j + 1) * 64 + (k + 32)]);
    }

    float du = 0.f, dv = 0.f;

    for (int sweep = 0; sweep < 16; ++sweep) {
        // exact norms at sweep start (kills incremental drift in the angles)
        {
            u64 a = 0ull, b = 0ull;
#pragma unroll
            for (int j = 0; j < 32; ++j) {
                a = fma2(U[j], U[j], a);
                b = fma2(V[j], V[j], b);
            }
            du = lo2(a) + hi2(a);
            dv = lo2(b) + hi2(b);
        }

        unsigned any = 0u;
        for (int g = 32; g >= 1; g >>= 1) {
            // cross rounds: pair (u_k, v_k), then shift v one lane within group
            const int src = (k & ~(g - 1)) | ((k + 1) & (g - 1));
            for (int r = 0; r < g; ++r) {
                u64 xx = 0ull;
#pragma unroll
                for (int j = 0; j < 32; ++j) xx = fma2(U[j], V[j], xx);
                float x = lo2(xx) + hi2(xx);

                bool rot = (x * x > 1e-13f * du * dv);
                any |= __ballot_sync(FULL, rot);

                float xd  = rot ? x : 1.0f;
                float tau = (dv - du) / (2.0f * xd);
                float t   = copysignf(1.0f, tau) /
                            (fabsf(tau) + sqrtf(fmaf(tau, tau, 1.0f)));
                float c   = rsqrtf(fmaf(t, t, 1.0f));
                float s   = t * c;
                if (!rot) { c = 1.0f; s = 0.0f; t = 0.0f; }

                float ndu = fmaf(-t, x, du);
                float ndv = fmaf( t, x, dv);

                u64 cc = pk2(c, c), ss = pk2(s, s), ns = pk2(-s, -s);
#pragma unroll
                for (int j = 0; j < 32; ++j) {
                    u64 un = fma2(cc, U[j], mul2(ns, V[j]));
                    u64 vn = fma2(cc, V[j], mul2(ss, U[j]));
                    U[j] = un;
                    V[j] = shfl64(vn, src);   // v ring-shifts; u stays put
                }
                du = ndu;
                dv = __shfl_sync(FULL, ndv, src);
            }

            // split: lower half-lanes keep the u-set, upper keep the v-set
            if (g > 1) {
                const int h = g >> 1;
                const bool low = (k & h) == 0;
#pragma unroll
                for (int j = 0; j < 32; ++j) {
                    u64 pu = shfl64x(U[j], h);
                    u64 pv = shfl64x(V[j], h);
                    if (low) V[j] = pu; else U[j] = pv;
                }
                float pdu = __shfl_xor_sync(FULL, du, h);
                float pdv = __shfl_xor_sync(FULL, dv, h);
                if (low) dv = pdu; else du = pdv;
            }
        }
        if (any == 0u) break;
    }

    // exact final norms -> log weights  g_p = 0.5*log(d_p)/d_p
    float fdu, fdv;
    {
        u64 a = 0ull, b = 0ull;
#pragma unroll
        for (int j = 0; j < 32; ++j) {
            a = fma2(U[j], U[j], a);
            b = fma2(V[j], V[j], b);
        }
        fdu = lo2(a) + hi2(a);
        fdv = lo2(b) + hi2(b);
    }

    __shared__ __align__(16) float W[64][66];   // even pad: 8B-aligned rows
    __shared__ float gw[64];
#pragma unroll
    for (int j = 0; j < 32; ++j) {
        W[k][2 * j]          = lo2(U[j]);
        W[k][2 * j + 1]      = hi2(U[j]);
        W[k + 32][2 * j]     = lo2(V[j]);
        W[k + 32][2 * j + 1] = hi2(V[j]);
    }
    gw[k]      = 0.5f * logf(fdu) / fdu;
    gw[k + 32] = 0.5f * logf(fdv) / fdv;
    __syncwarp();

    // X = sum_p g_p w_p w_p^T ; lane k emits output columns k and k+32
    u64 acc[32];
#pragma unroll
    for (int j = 0; j < 32; ++j) acc[j] = 0ull;
    for (int p = 0; p < 64; ++p) {
        float sp = gw[p] * W[p][k];
        u64 sp2 = pk2(sp, sp);
        const u64* row = (const u64*)&W[p][0];
#pragma unroll
        for (int j = 0; j < 32; ++j) acc[j] = fma2(sp2, row[j], acc[j]);
    }
#pragma unroll
    for (int j = 0; j < 32; ++j) {
        Xm[(2 * j) * 64 + k]     = lo2(acc[j]);
        Xm[(2 * j + 1) * 64 + k] = hi2(acc[j]);
    }

#pragma unroll
    for (int j = 0; j < 32; ++j) acc[j] = 0ull;
    for (int p = 0; p < 64; ++p) {
        float sp = gw[p] * W[p][k + 32];
        u64 sp2 = pk2(sp, sp);
        const u64* row = (const u64*)&W[p][0];
#pragma unroll
        for (int j = 0; j < 32; ++j) acc[j] = fma2(sp2, row[j], acc[j]);
    }
#pragma unroll
    for (int j = 0; j < 32; ++j) {
        Xm[(2 * j) * 64 + (k + 32)]     = lo2(acc[j]);
        Xm[(2 * j + 1) * 64 + (k + 32)] = hi2(acc[j]);
    }
}

extern "C" void kernel_launch(void* const* d_in, const int* in_sizes, int n_in,
                              void* d_out, int out_size) {
    const float* P = (const float*)d_in[0];
    float* X = (float*)d_out;
    int nmat = in_sizes[0] / 4096;
    logeig_jacobi<<<nmat, 32>>>(P, X, nmat);
}

// round 3
// speedup vs baseline: 1.4699x; 1.0937x over previous
#include <cuda_runtime.h>
#include <math.h>

#define FULL 0xFFFFFFFFu
typedef unsigned long long u64;

// ---- packed f32x2 helpers (sm_103a) ------------------------------------
__device__ __forceinline__ u64 pk2(float lo, float hi) {
    u64 r; asm("mov.b64 %0, {%1, %2};" : "=l"(r) : "f"(lo), "f"(hi)); return r;
}
__device__ __forceinline__ float lo2(u64 x) { return __uint_as_float((unsigned)x); }
__device__ __forceinline__ float hi2(u64 x) { return __uint_as_float((unsigned)(x >> 32)); }
__device__ __forceinline__ u64 fma2(u64 a, u64 b, u64 c) {
    u64 d; asm("fma.rn.f32x2 %0, %1, %2, %3;" : "=l"(d) : "l"(a), "l"(b), "l"(c)); return d;
}
__device__ __forceinline__ u64 mul2(u64 a, u64 b) {
    u64 d; asm("mul.rn.f32x2 %0, %1, %2;" : "=l"(d) : "l"(a), "l"(b)); return d;
}
__device__ __forceinline__ u64 add2(u64 a, u64 b) {
    u64 d; asm("add.rn.f32x2 %0, %1, %2;" : "=l"(d) : "l"(a), "l"(b)); return d;
}
__device__ __forceinline__ u64 shfl64(u64 x, int src) {
    unsigned lo = (unsigned)x, hi = (unsigned)(x >> 32);
    lo = __shfl_sync(FULL, lo, src);
    hi = __shfl_sync(FULL, hi, src);
    return ((u64)hi << 32) | (u64)lo;
}
__device__ __forceinline__ u64 shfl64x(u64 x, int mask) {
    unsigned lo = (unsigned)x, hi = (unsigned)(x >> 32);
    lo = __shfl_xor_sync(FULL, lo, mask);
    hi = __shfl_xor_sync(FULL, hi, mask);
    return ((u64)hi << 32) | (u64)lo;
}
__device__ __forceinline__ float red2(u64 a, u64 b, u64 c, u64 d) {
    u64 s = add2(add2(a, b), add2(c, d));
    return lo2(s) + hi2(s);
}

// One warp per 64x64 SPD matrix. Lane k holds two columns (u, v) packed as
// 32 x f32x2. One-sided Jacobi, recursive-halving tournament. The dot for
// the NEXT pairing is fused into the rotation loop (post-shuffle), so the
// per-round critical path is just angle -> rotation -> angle.
__global__ __launch_bounds__(32) void logeig_jacobi(const float* __restrict__ P,
                                                    float* __restrict__ X,
                                                    int nmat) {
    const int m = blockIdx.x;
    if (m >= nmat) return;
    const int k = threadIdx.x;
    const float* __restrict__ Pm = P + (size_t)m * 4096;
    float* __restrict__ Xm = X + (size_t)m * 4096;

    u64 U[32], V[32];
#pragma unroll
    for (int j = 0; j < 32; ++j) {
        U[j] = pk2(Pm[(2 * j) * 64 + k],        Pm[(2 * j + 1) * 64 + k]);
        V[j] = pk2(Pm[(2 * j) * 64 + (k + 32)], Pm[(2 * j + 1) * 64 + (k + 32)]);
    }

    float du = 0.f, dv = 0.f;

    for (int sweep = 0; sweep < 16; ++sweep) {
        // exact norms at sweep start (4 chains)
        {
            u64 a0 = 0, a1 = 0, b0 = 0, b1 = 0;
#pragma unroll
            for (int j = 0; j < 32; j += 2) {
                a0 = fma2(U[j], U[j], a0);     a1 = fma2(U[j + 1], U[j + 1], a1);
                b0 = fma2(V[j], V[j], b0);     b1 = fma2(V[j + 1], V[j + 1], b1);
            }
            u64 a = add2(a0, a1), b = add2(b0, b1);
            du = lo2(a) + hi2(a);
            dv = lo2(b) + hi2(b);
        }

        int anyl = 0;                      // per-lane flag; one ballot per sweep
        for (int g = 32; g >= 1; g >>= 1) {
            const int src = (k & ~(g - 1)) | ((k + 1) & (g - 1));

            // fresh dot at level start (4 chains)
            float x;
            {
                u64 x0 = 0, x1 = 0, x2 = 0, x3 = 0;
#pragma unroll
                for (int j = 0; j < 32; j += 4) {
                    x0 = fma2(U[j],     V[j],     x0);
                    x1 = fma2(U[j + 1], V[j + 1], x1);
                    x2 = fma2(U[j + 2], V[j + 2], x2);
                    x3 = fma2(U[j + 3], V[j + 3], x3);
                }
                x = red2(x0, x1, x2, x3);
            }

            for (int r = 0; r < g; ++r) {
                bool rot = (x * x > 1e-10f * du * dv);
                anyl |= (int)rot;

                float xd  = rot ? x : 1.0f;
                float tau = __fdividef(dv - du, 2.0f * xd);
                float t   = __fdividef(copysignf(1.0f, tau),
                                       fabsf(tau) + sqrtf(fmaf(tau, tau, 1.0f)));
                float c   = rsqrtf(fmaf(t, t, 1.0f));
                float s   = t * c;
                if (!rot) { c = 1.0f; s = 0.0f; t = 0.0f; }

                float ndu = fmaf(-t, x, du);
                float ndv = fmaf( t, x, dv);

                u64 cc = pk2(c, c), ss = pk2(s, s), ns = pk2(-s, -s);
                u64 x0 = 0, x1 = 0, x2 = 0, x3 = 0;   // fused next-round dot
#pragma unroll
                for (int j = 0; j < 32; ++j) {
                    u64 un = fma2(cc, U[j], mul2(ns, V[j]));
                    u64 vn = fma2(cc, V[j], mul2(ss, U[j]));
                    U[j] = un;
                    V[j] = shfl64(vn, src);
                    if ((j & 3) == 0)      x0 = fma2(un, V[j], x0);
                    else if ((j & 3) == 1) x1 = fma2(un, V[j], x1);
                    else if ((j & 3) == 2) x2 = fma2(un, V[j], x2);
                    else                   x3 = fma2(un, V[j], x3);
                }
                du = ndu;
                dv = __shfl_sync(FULL, ndv, src);
                x = red2(x0, x1, x2, x3);
            }

            // split: lower half-lanes keep u-set, upper keep v-set
            if (g > 1) {
                const int h = g >> 1;
                const bool low = (k & h) == 0;
#pragma unroll
                for (int j = 0; j < 32; ++j) {
                    u64 pu = shfl64x(U[j], h);
                    u64 pv = shfl64x(V[j], h);
                    if (low) V[j] = pu; else U[j] = pv;
                }
                float pdu = __shfl_xor_sync(FULL, du, h);
                float pdv = __shfl_xor_sync(FULL, dv, h);
                if (low) dv = pdu; else du = pdv;
            }
        }
        if (__ballot_sync(FULL, anyl) == 0u) break;
    }

    // exact final norms -> log weights  g_p = 0.5*log(d_p)/d_p
    float fdu, fdv;
    {
        u64 a0 = 0, a1 = 0, b0 = 0, b1 = 0;
#pragma unroll
        for (int j = 0; j < 32; j += 2) {
            a0 = fma2(U[j], U[j], a0);     a1 = fma2(U[j + 1], U[j + 1], a1);
            b0 = fma2(V[j], V[j], b0);     b1 = fma2(V[j + 1], V[j + 1], b1);
        }
        u64 a = add2(a0, a1), b = add2(b0, b1);
        fdu = lo2(a) + hi2(a);
        fdv = lo2(b) + hi2(b);
    }

    __shared__ __align__(16) float W[64][66];
    __shared__ float gw[64];
#pragma unroll
    for (int j = 0; j < 32; ++j) {
        W[k][2 * j]          = lo2(U[j]);
        W[k][2 * j + 1]      = hi2(U[j]);
        W[k + 32][2 * j]     = lo2(V[j]);
        W[k + 32][2 * j + 1] = hi2(V[j]);
    }
    gw[k]      = 0.5f * logf(fdu) / fdu;
    gw[k + 32] = 0.5f * logf(fdv) / fdv;
    __syncwarp();

    // X = sum_p g_p w_p w_p^T ; lane k emits output columns k and k+32
    u64 acc[32];
#pragma unroll
    for (int j = 0; j < 32; ++j) acc[j] = 0ull;
    for (int p = 0; p < 64; ++p) {
        float sp = gw[p] * W[p][k];
        u64 sp2 = pk2(sp, sp);
        const u64* row = (const u64*)&W[p][0];
#pragma unroll
        for (int j = 0; j < 32; ++j) acc[j] = fma2(sp2, row[j], acc[j]);
    }
#pragma unroll
    for (int j = 0; j < 32; ++j) {
        Xm[(2 * j) * 64 + k]     = lo2(acc[j]);
        Xm[(2 * j + 1) * 64 + k] = hi2(acc[j]);
    }

#pragma unroll
    for (int j = 0; j < 32; ++j) acc[j] = 0ull;
    for (int p = 0; p < 64; ++p) {
        float sp = gw[p] * W[p][k + 32];
        u64 sp2 = pk2(sp, sp);
        const u64* row = (const u64*)&W[p][0];
#pragma unroll
        for (int j = 0; j < 32; ++j) acc[j] = fma2(sp2, row[j], acc[j]);
    }
#pragma unroll
    for (int j = 0; j < 32; ++j) {
        Xm[(2 * j) * 64 + (k + 32)]     = lo2(acc[j]);
        Xm[(2 * j + 1) * 64 + (k + 32)] = hi2(acc[j]);
    }
}

extern "C" void kernel_launch(void* const* d_in, const int* in_sizes, int n_in,
                              void* d_out, int out_size) {
    const float* P = (const float*)d_in[0];
    float* X = (float*)d_out;
    int nmat = in_sizes[0] / 4096;
    logeig_jacobi<<<nmat, 32>>>(P, X, nmat);
}

// round 5
// speedup vs baseline: 1.7446x; 1.1869x over previous
#include <cuda_runtime.h>
#include <math.h>

#define FULL 0xFFFFFFFFu
typedef unsigned long long u64;

// ---- packed f32x2 helpers (sm_103a) ------------------------------------
__device__ __forceinline__ u64 pk2(float lo, float hi) {
    u64 r; asm("mov.b64 %0, {%1, %2};" : "=l"(r) : "f"(lo), "f"(hi)); return r;
}
__device__ __forceinline__ float lo2(u64 x) { return __uint_as_float((unsigned)x); }
__device__ __forceinline__ float hi2(u64 x) { return __uint_as_float((unsigned)(x >> 32)); }
__device__ __forceinline__ u64 fma2(u64 a, u64 b, u64 c) {
    u64 d; asm("fma.rn.f32x2 %0, %1, %2, %3;" : "=l"(d) : "l"(a), "l"(b), "l"(c)); return d;
}
__device__ __forceinline__ u64 mul2(u64 a, u64 b) {
    u64 d; asm("mul.rn.f32x2 %0, %1, %2;" : "=l"(d) : "l"(a), "l"(b)); return d;
}
__device__ __forceinline__ u64 add2(u64 a, u64 b) {
    u64 d; asm("add.rn.f32x2 %0, %1, %2;" : "=l"(d) : "l"(a), "l"(b)); return d;
}
__device__ __forceinline__ u64 shfl64(u64 x, int src) {
    unsigned lo = (unsigned)x, hi = (unsigned)(x >> 32);
    lo = __shfl_sync(FULL, lo, src);
    hi = __shfl_sync(FULL, hi, src);
    return ((u64)hi << 32) | (u64)lo;
}
__device__ __forceinline__ u64 shfl64x(u64 x, int mask) {
    unsigned lo = (unsigned)x, hi = (unsigned)(x >> 32);
    lo = __shfl_xor_sync(FULL, lo, mask);
    hi = __shfl_xor_sync(FULL, hi, mask);
    return ((u64)hi << 32) | (u64)lo;
}
__device__ __forceinline__ float red2(u64 a, u64 b, u64 c, u64 d) {
    u64 s = add2(add2(a, b), add2(c, d));
    return lo2(s) + hi2(s);
}

// One warp per 64x64 SPD matrix. Lane k holds two columns (u, v) packed as
// 32 x f32x2. One-sided Jacobi, recursive-halving tournament, fused
// next-pairing dot, and a cheap "skip" path for rounds where no lane
// rotates (ring-advance + dot only). Cap 16 sweeps: the Wishart spectrum
// here needs ~13-16 (10 was measured insufficient: rel_err 0.099).
__global__ __launch_bounds__(32) void logeig_jacobi(const float* __restrict__ P,
                                                    float* __restrict__ X,
                                                    int nmat) {
    const int m = blockIdx.x;
    if (m >= nmat) return;
    const int k = threadIdx.x;
    const float* __restrict__ Pm = P + (size_t)m * 4096;
    float* __restrict__ Xm = X + (size_t)m * 4096;

    u64 U[32], V[32];
#pragma unroll
    for (int j = 0; j < 32; ++j) {
        U[j] = pk2(Pm[(2 * j) * 64 + k],        Pm[(2 * j + 1) * 64 + k]);
        V[j] = pk2(Pm[(2 * j) * 64 + (k + 32)], Pm[(2 * j + 1) * 64 + (k + 32)]);
    }

    float du = 0.f, dv = 0.f;

    for (int sweep = 0; sweep < 16; ++sweep) {
        // exact norms at sweep start
        {
            u64 a0 = 0, a1 = 0, b0 = 0, b1 = 0;
#pragma unroll
            for (int j = 0; j < 32; j += 2) {
                a0 = fma2(U[j], U[j], a0);     a1 = fma2(U[j + 1], U[j + 1], a1);
                b0 = fma2(V[j], V[j], b0);     b1 = fma2(V[j + 1], V[j + 1], b1);
            }
            u64 a = add2(a0, a1), b = add2(b0, b1);
            du = lo2(a) + hi2(a);
            dv = lo2(b) + hi2(b);
        }

        unsigned any = 0u;
        for (int g = 32; g >= 1; g >>= 1) {
            const int src = (k & ~(g - 1)) | ((k + 1) & (g - 1));

            // fresh dot at level start
            float x;
            {
                u64 x0 = 0, x1 = 0, x2 = 0, x3 = 0;
#pragma unroll
                for (int j = 0; j < 32; j += 4) {
                    x0 = fma2(U[j],     V[j],     x0);
                    x1 = fma2(U[j + 1], V[j + 1], x1);
                    x2 = fma2(U[j + 2], V[j + 2], x2);
                    x3 = fma2(U[j + 3], V[j + 3], x3);
                }
                x = red2(x0, x1, x2, x3);
            }

            for (int r = 0; r < g; ++r) {
                bool rot = (x * x > 1e-9f * du * dv);
                unsigned bal = __ballot_sync(FULL, rot);
                any |= bal;

                u64 x0 = 0, x1 = 0, x2 = 0, x3 = 0;
                if (bal) {
                    // full path: rotate, ring-advance, fused next dot
                    float xd  = rot ? x : 1.0f;
                    float tau = __fdividef(dv - du, 2.0f * xd);
                    float t   = __fdividef(copysignf(1.0f, tau),
                                           fabsf(tau) + sqrtf(fmaf(tau, tau, 1.0f)));
                    float c   = rsqrtf(fmaf(t, t, 1.0f));
                    float s   = t * c;
                    if (!rot) { c = 1.0f; s = 0.0f; t = 0.0f; }

                    float ndu = fmaf(-t, x, du);
                    float ndv = fmaf( t, x, dv);

                    u64 cc = pk2(c, c), ss = pk2(s, s), ns = pk2(-s, -s);
#pragma unroll
                    for (int j = 0; j < 32; ++j) {
                        u64 un = fma2(cc, U[j], mul2(ns, V[j]));
                        u64 vn = fma2(cc, V[j], mul2(ss, U[j]));
                        U[j] = un;
                        V[j] = shfl64(vn, src);
                        if ((j & 3) == 0)      x0 = fma2(un, V[j], x0);
                        else if ((j & 3) == 1) x1 = fma2(un, V[j], x1);
                        else if ((j & 3) == 2) x2 = fma2(un, V[j], x2);
                        else                   x3 = fma2(un, V[j], x3);
                    }
                    du = ndu;
                    dv = __shfl_sync(FULL, ndv, src);
                } else {
                    // skip path: no lane rotates -> just advance pairing + dot
#pragma unroll
                    for (int j = 0; j < 32; ++j) {
                        V[j] = shfl64(V[j], src);
                        if ((j & 3) == 0)      x0 = fma2(U[j], V[j], x0);
                        else if ((j & 3) == 1) x1 = fma2(U[j], V[j], x1);
                        else if ((j & 3) == 2) x2 = fma2(U[j], V[j], x2);
                        else                   x3 = fma2(U[j], V[j], x3);
                    }
                    dv = __shfl_sync(FULL, dv, src);
                }
                x = red2(x0, x1, x2, x3);
            }

            // split: lower half-lanes keep u-set, upper keep v-set
            if (g > 1) {
                const int h = g >> 1;
                const bool low = (k & h) == 0;
#pragma unroll
                for (int j = 0; j < 32; ++j) {
                    u64 pu = shfl64x(U[j], h);
                    u64 pv = shfl64x(V[j], h);
                    if (low) V[j] = pu; else U[j] = pv;
                }
                float pdu = __shfl_xor_sync(FULL, du, h);
                float pdv = __shfl_xor_sync(FULL, dv, h);
                if (low) dv = pdu; else du = pdv;
            }
        }
        if (any == 0u) break;
    }

    // exact final norms -> log weights  g_p = 0.5*log(d_p)/d_p
    float fdu, fdv;
    {
        u64 a0 = 0, a1 = 0, b0 = 0, b1 = 0;
#pragma unroll
        for (int j = 0; j < 32; j += 2) {
            a0 = fma2(U[j], U[j], a0);     a1 = fma2(U[j + 1], U[j + 1], a1);
            b0 = fma2(V[j], V[j], b0);     b1 = fma2(V[j + 1], V[j + 1], b1);
        }
        u64 a = add2(a0, a1), b = add2(b0, b1);
        fdu = lo2(a) + hi2(a);
        fdv = lo2(b) + hi2(b);
    }

    __shared__ __align__(16) float W[64][66];
    __shared__ float gw[64];
#pragma unroll
    for (int j = 0; j < 32; ++j) {
        W[k][2 * j]          = lo2(U[j]);
        W[k][2 * j + 1]      = hi2(U[j]);
        W[k + 32][2 * j]     = lo2(V[j]);
        W[k + 32][2 * j + 1] = hi2(V[j]);
    }
    gw[k]      = 0.5f * __logf(fdu) / fdu;
    gw[k + 32] = 0.5f * __logf(fdv) / fdv;
    __syncwarp();

    // X = sum_p g_p w_p w_p^T ; lane k emits output columns k and k+32
    u64 acc[32];
#pragma unroll
    for (int j = 0; j < 32; ++j) acc[j] = 0ull;
    for (int p = 0; p < 64; ++p) {
        float sp = gw[p] * W[p][k];
        u64 sp2 = pk2(sp, sp);
        const u64* row = (const u64*)&W[p][0];
#pragma unroll
        for (int j = 0; j < 32; ++j) acc[j] = fma2(sp2, row[j], acc[j]);
    }
#pragma unroll
    for (int j = 0; j < 32; ++j) {
        Xm[(2 * j) * 64 + k]     = lo2(acc[j]);
        Xm[(2 * j + 1) * 64 + k] = hi2(acc[j]);
    }

#pragma unroll
    for (int j = 0; j < 32; ++j) acc[j] = 0ull;
    for (int p = 0; p < 64; ++p) {
        float sp = gw[p] * W[p][k + 32];
        u64 sp2 = pk2(sp, sp);
        const u64* row = (const u64*)&W[p][0];
#pragma unroll
        for (int j = 0; j < 32; ++j) acc[j] = fma2(sp2, row[j], acc[j]);
    }
#pragma unroll
    for (int j = 0; j < 32; ++j) {
        Xm[(2 * j) * 64 + (k + 32)]     = lo2(acc[j]);
        Xm[(2 * j + 1) * 64 + (k + 32)] = hi2(acc[j]);
    }
}

extern "C" void kernel_launch(void* const* d_in, const int* in_sizes, int n_in,
                              void* d_out, int out_size) {
    const float* P = (const float*)d_in[0];
    float* X = (float*)d_out;
    int nmat = in_sizes[0] / 4096;
    logeig_jacobi<<<nmat, 32>>>(P, X, nmat);
}

// round 6
// speedup vs baseline: 1.9672x; 1.1276x over previous
#include <cuda_runtime.h>
#include <math.h>

#define FULL 0xFFFFFFFFu
typedef unsigned long long u64;

// ---- packed f32x2 helpers (sm_103a) ------------------------------------
__device__ __forceinline__ u64 pk2(float lo, float hi) {
    u64 r; asm("mov.b64 %0, {%1, %2};" : "=l"(r) : "f"(lo), "f"(hi)); return r;
}
__device__ __forceinline__ float lo2(u64 x) { return __uint_as_float((unsigned)x); }
__device__ __forceinline__ float hi2(u64 x) { return __uint_as_float((unsigned)(x >> 32)); }
__device__ __forceinline__ u64 fma2(u64 a, u64 b, u64 c) {
    u64 d; asm("fma.rn.f32x2 %0, %1, %2, %3;" : "=l"(d) : "l"(a), "l"(b), "l"(c)); return d;
}
__device__ __forceinline__ u64 mul2(u64 a, u64 b) {
    u64 d; asm("mul.rn.f32x2 %0, %1, %2;" : "=l"(d) : "l"(a), "l"(b)); return d;
}
__device__ __forceinline__ u64 add2(u64 a, u64 b) {
    u64 d; asm("add.rn.f32x2 %0, %1, %2;" : "=l"(d) : "l"(a), "l"(b)); return d;
}
__device__ __forceinline__ u64 shfl64(u64 x, int src) {
    unsigned lo = (unsigned)x, hi = (unsigned)(x >> 32);
    lo = __shfl_sync(FULL, lo, src);
    hi = __shfl_sync(FULL, hi, src);
    return ((u64)hi << 32) | (u64)lo;
}
__device__ __forceinline__ u64 shfl64x(u64 x, int mask) {
    unsigned lo = (unsigned)x, hi = (unsigned)(x >> 32);
    lo = __shfl_xor_sync(FULL, lo, mask);
    hi = __shfl_xor_sync(FULL, hi, mask);
    return ((u64)hi << 32) | (u64)lo;
}
__device__ __forceinline__ float red2(u64 a, u64 b, u64 c, u64 d) {
    u64 s = add2(add2(a, b), add2(c, d));
    return lo2(s) + hi2(s);
}

// One warp per 64x64 SPD matrix. Lane k holds two columns (u, v) packed as
// 32 x f32x2. One-sided Jacobi, recursive-halving tournament, fused
// next-pairing dot, ballot-gated cheap "skip" rounds. Cap 16 sweeps (10 is
// insufficient for this spectrum: measured rel_err 0.099).
// __launch_bounds__(32, 12): cap at 170 regs -> 3 warps/SMSP (was 2 at 228).
__global__ __launch_bounds__(32, 12) void logeig_jacobi(const float* __restrict__ P,
                                                        float* __restrict__ X,
                                                        int nmat) {
    const int m = blockIdx.x;
    if (m >= nmat) return;
    const int k = threadIdx.x;
    const float* __restrict__ Pm = P + (size_t)m * 4096;
    float* __restrict__ Xm = X + (size_t)m * 4096;

    u64 U[32], V[32];
#pragma unroll
    for (int j = 0; j < 32; ++j) {
        U[j] = pk2(Pm[(2 * j) * 64 + k],        Pm[(2 * j + 1) * 64 + k]);
        V[j] = pk2(Pm[(2 * j) * 64 + (k + 32)], Pm[(2 * j + 1) * 64 + (k + 32)]);
    }

    float du = 0.f, dv = 0.f;

    for (int sweep = 0; sweep < 16; ++sweep) {
        // exact norms at sweep start
        {
            u64 a0 = 0, a1 = 0, b0 = 0, b1 = 0;
#pragma unroll
            for (int j = 0; j < 32; j += 2) {
                a0 = fma2(U[j], U[j], a0);     a1 = fma2(U[j + 1], U[j + 1], a1);
                b0 = fma2(V[j], V[j], b0);     b1 = fma2(V[j + 1], V[j + 1], b1);
            }
            u64 a = add2(a0, a1), b = add2(b0, b1);
            du = lo2(a) + hi2(a);
            dv = lo2(b) + hi2(b);
        }

        unsigned any = 0u;
        for (int g = 32; g >= 1; g >>= 1) {
            const int src = (k & ~(g - 1)) | ((k + 1) & (g - 1));

            // fresh dot at level start
            float x;
            {
                u64 x0 = 0, x1 = 0, x2 = 0, x3 = 0;
#pragma unroll
                for (int j = 0; j < 32; j += 4) {
                    x0 = fma2(U[j],     V[j],     x0);
                    x1 = fma2(U[j + 1], V[j + 1], x1);
                    x2 = fma2(U[j + 2], V[j + 2], x2);
                    x3 = fma2(U[j + 3], V[j + 3], x3);
                }
                x = red2(x0, x1, x2, x3);
            }

            for (int r = 0; r < g; ++r) {
                bool rot = (x * x > 1e-8f * du * dv);
                unsigned bal = __ballot_sync(FULL, rot);
                any |= bal;

                u64 x0 = 0, x1 = 0, x2 = 0, x3 = 0;
                if (bal) {
                    // full path: rotate, ring-advance, fused next dot
                    float xd  = rot ? x : 1.0f;
                    float tau = __fdividef(dv - du, 2.0f * xd);
                    float t   = __fdividef(copysignf(1.0f, tau),
                                           fabsf(tau) + sqrtf(fmaf(tau, tau, 1.0f)));
                    float c   = rsqrtf(fmaf(t, t, 1.0f));
                    float s   = t * c;
                    if (!rot) { c = 1.0f; s = 0.0f; t = 0.0f; }

                    float ndu = fmaf(-t, x, du);
                    float ndv = fmaf( t, x, dv);

                    u64 cc = pk2(c, c), ss = pk2(s, s), ns = pk2(-s, -s);
#pragma unroll
                    for (int j = 0; j < 32; ++j) {
                        u64 un = fma2(cc, U[j], mul2(ns, V[j]));
                        u64 vn = fma2(cc, V[j], mul2(ss, U[j]));
                        U[j] = un;
                        V[j] = shfl64(vn, src);
                        if ((j & 3) == 0)      x0 = fma2(un, V[j], x0);
                        else if ((j & 3) == 1) x1 = fma2(un, V[j], x1);
                        else if ((j & 3) == 2) x2 = fma2(un, V[j], x2);
                        else                   x3 = fma2(un, V[j], x3);
                    }
                    du = ndu;
                    dv = __shfl_sync(FULL, ndv, src);
                } else {
                    // skip path: no lane rotates -> just advance pairing + dot
#pragma unroll
                    for (int j = 0; j < 32; ++j) {
                        V[j] = shfl64(V[j], src);
                        if ((j & 3) == 0)      x0 = fma2(U[j], V[j], x0);
                        else if ((j & 3) == 1) x1 = fma2(U[j], V[j], x1);
                        else if ((j & 3) == 2) x2 = fma2(U[j], V[j], x2);
                        else                   x3 = fma2(U[j], V[j], x3);
                    }
                    dv = __shfl_sync(FULL, dv, src);
                }
                x = red2(x0, x1, x2, x3);
            }

            // split: lower half-lanes keep u-set, upper keep v-set
            if (g > 1) {
                const int h = g >> 1;
                const bool low = (k & h) == 0;
#pragma unroll
                for (int j = 0; j < 32; ++j) {
                    u64 pu = shfl64x(U[j], h);
                    u64 pv = shfl64x(V[j], h);
                    if (low) V[j] = pu; else U[j] = pv;
                }
                float pdu = __shfl_xor_sync(FULL, du, h);
                float pdv = __shfl_xor_sync(FULL, dv, h);
                if (low) dv = pdu; else du = pdv;
            }
        }
        if (any == 0u) break;
    }

    // exact final norms -> log weights  g_p = 0.5*log(d_p)/d_p
    float fdu, fdv;
    {
        u64 a0 = 0, a1 = 0, b0 = 0, b1 = 0;
#pragma unroll
        for (int j = 0; j < 32; j += 2) {
            a0 = fma2(U[j], U[j], a0);     a1 = fma2(U[j + 1], U[j + 1], a1);
            b0 = fma2(V[j], V[j], b0);     b1 = fma2(V[j + 1], V[j + 1], b1);
        }
        u64 a = add2(a0, a1), b = add2(b0, b1);
        fdu = lo2(a) + hi2(a);
        fdv = lo2(b) + hi2(b);
    }

    __shared__ __align__(16) float W[64][66];
    __shared__ float gw[64];
#pragma unroll
    for (int j = 0; j < 32; ++j) {
        W[k][2 * j]          = lo2(U[j]);
        W[k][2 * j + 1]      = hi2(U[j]);
        W[k + 32][2 * j]     = lo2(V[j]);
        W[k + 32][2 * j + 1] = hi2(V[j]);
    }
    gw[k]      = 0.5f * __logf(fdu) / fdu;
    gw[k + 32] = 0.5f * __logf(fdv) / fdv;
    __syncwarp();

    // X = sum_p g_p w_p w_p^T ; lane k emits columns k and k+32, in
    // 16-wide row quarters to keep peak register pressure under the cap.
#pragma unroll
    for (int half = 0; half < 2; ++half) {
        const int col = k + 32 * half;
#pragma unroll
        for (int q = 0; q < 2; ++q) {
            u64 acc[16];
#pragma unroll
            for (int j = 0; j < 16; ++j) acc[j] = 0ull;
            for (int p = 0; p < 64; ++p) {
                float sp = gw[p] * W[p][col];
                u64 sp2 = pk2(sp, sp);
                const u64* row = (const u64*)&W[p][0] + 16 * q;
#pragma unroll
                for (int j = 0; j < 16; ++j) acc[j] = fma2(sp2, row[j], acc[j]);
            }
#pragma unroll
            for (int j = 0; j < 16; ++j) {
                Xm[(32 * q + 2 * j) * 64 + col]     = lo2(acc[j]);
                Xm[(32 * q + 2 * j + 1) * 64 + col] = hi2(acc[j]);
            }
        }
    }
}

extern "C" void kernel_launch(void* const* d_in, const int* in_sizes, int n_in,
                              void* d_out, int out_size) {
    const float* P = (const float*)d_in[0];
    float* X = (float*)d_out;
    int nmat = in_sizes[0] / 4096;
    logeig_jacobi<<<nmat, 32>>>(P, X, nmat);
}